// round 3
// baseline (speedup 1.0000x reference)
#include <cuda_runtime.h>
#include <cuda_fp16.h>
#include <cstdint>

#define BB   32
#define CIN  128
#define COUT 256
#define HH   64
#define WW   64
#define HP   66   // padded spatial

// Padded HWC fp16 input, per-pixel XOR-swizzled for conflict-free ldmatrix:
// pixel (padded row pr, padded col pc) of image b lives at halves
//   base = ((b*HP + pr)*HP + pc)*CIN ; within pixel, 16B chunk c stored at
//   chunk (c ^ ((pr*HP+pc)&7))  (XOR affects low 3 bits only).
__device__ __align__(256) __half g_Xp[(size_t)BB * HP * HP * CIN];
// Weights: [shift 0..8][cout 0..255][cin 0..127] fp16, chunk-swizzled by (cout&7).
__device__ __align__(256) __half g_Wsw[9 * COUT * CIN];

// ------------------------------ small helpers ------------------------------

__device__ __forceinline__ uint32_t smem_u32(const void* p) {
    uint32_t a;
    asm("{ .reg .u64 t; cvta.to.shared.u64 t, %1; cvt.u32.u64 %0, t; }" : "=r"(a) : "l"(p));
    return a;
}

__device__ __forceinline__ void cpa16(uint32_t dst, const void* src) {
    asm volatile("cp.async.cg.shared.global [%0], [%1], 16;" :: "r"(dst), "l"(src));
}
#define CP_COMMIT() asm volatile("cp.async.commit_group;" ::: "memory")
#define CP_WAIT(N)  asm volatile("cp.async.wait_group %0;" :: "n"(N) : "memory")

__device__ __forceinline__ void ldsm4(uint32_t* r, uint32_t addr) {
    asm volatile("ldmatrix.sync.aligned.m8n8.x4.shared.b16 {%0,%1,%2,%3}, [%4];"
        : "=r"(r[0]), "=r"(r[1]), "=r"(r[2]), "=r"(r[3]) : "r"(addr));
}

__device__ __forceinline__ void mma16816(float* d, const uint32_t* a, const uint32_t* b) {
    asm volatile(
        "mma.sync.aligned.m16n8k16.row.col.f32.f16.f16.f32 "
        "{%0,%1,%2,%3}, {%4,%5,%6,%7}, {%8,%9}, {%0,%1,%2,%3};"
        : "+f"(d[0]), "+f"(d[1]), "+f"(d[2]), "+f"(d[3])
        : "r"(a[0]), "r"(a[1]), "r"(a[2]), "r"(a[3]), "r"(b[0]), "r"(b[1]));
}

// ------------------------------ prepass kernels ------------------------------

__global__ void k_zero_xp() {
    const size_t n = (size_t)BB * HP * HP * CIN / 8;  // uint4 count
    uint4 z = make_uint4(0, 0, 0, 0);
    uint4* p = reinterpret_cast<uint4*>(g_Xp);
    for (size_t i = (size_t)blockIdx.x * blockDim.x + threadIdx.x; i < n;
         i += (size_t)gridDim.x * blockDim.x)
        p[i] = z;
}

// One block per (b, h): NCHW fp32 row -> padded HWC fp16 (swizzled) via SMEM transpose.
__global__ void k_fill_xp(const float* __restrict__ X) {
    __shared__ float s[CIN * 65];  // stride 65 kills bank conflicts
    int b = blockIdx.x >> 6;
    int h = blockIdx.x & 63;
    const float* src = X + (size_t)b * CIN * HH * WW + (size_t)h * WW;
    for (int e = threadIdx.x; e < CIN * WW; e += blockDim.x) {
        int ci = e >> 6, w = e & 63;
        s[ci * 65 + w] = src[(size_t)ci * HH * WW + w];
    }
    __syncthreads();
    int pr = h + 1;
    for (int o = threadIdx.x; o < WW * CIN / 2; o += blockDim.x) {
        int w  = o >> 6;
        int cp = (o & 63) * 2;          // even channel index
        int pc = w + 1;
        int key = ((pr * HP) + pc) & 7;
        __half2 v = __floats2half2_rn(s[cp * 65 + w], s[(cp + 1) * 65 + w]);
        size_t base = ((size_t)(b * HP + pr) * HP + pc) * CIN;
        int off = (((cp >> 3) ^ key) << 3) + (cp & 7);   // halves within pixel
        *reinterpret_cast<__half2*>(g_Xp + base + off) = v;
    }
}

// Weights OIHW fp32 -> [s][cout][cin] fp16 with chunk swizzle by cout&7.
__global__ void k_prep_w(const float* __restrict__ W) {
    int idx = blockIdx.x * blockDim.x + threadIdx.x;
    if (idx >= 9 * COUT * CIN) return;
    int s  = idx / (COUT * CIN);
    int r  = idx - s * (COUT * CIN);
    int co = r >> 7;
    int ci = r & 127;
    int kh = s / 3, kw = s - kh * 3;
    float v = W[((size_t)(co * CIN + ci) * 3 + kh) * 3 + kw];
    uint32_t byte = (uint32_t)(s * COUT + co) * 256u
                  + ((((uint32_t)ci >> 3) ^ ((uint32_t)co & 7)) << 4)
                  + ((uint32_t)ci & 7) * 2u;
    *reinterpret_cast<__half*>(reinterpret_cast<char*>(g_Wsw) + byte) = __float2half_rn(v);
}

// ------------------------------ main conv kernel ------------------------------
// CTA: 256 pixels (4 output rows of one image) x 128 couts (half of COUT).
// 8 warps (4 m-groups x 2 n-groups), warp tile 64x64 via mma.sync m16n8k16.
// SMEM: rows buffer 6x66x256B = 101376 | W triple buffer 3x32768 = 98304.

#define SMEM_ROWS  0
#define SMEM_W     101376
#define WBUF_SZ    32768
#define SMEM_TOTAL (101376 + 3 * WBUF_SZ)   // 199680 bytes

__global__ void __launch_bounds__(256, 1)
k_conv(float* __restrict__ out, const float* __restrict__ bias) {
    extern __shared__ char smem[];
    const uint32_t sb = smem_u32(smem);
    const uint32_t sRows = sb + SMEM_ROWS;
    const uint32_t sW    = sb + SMEM_W;

    const int tid = threadIdx.x;
    const int wid = tid >> 5;
    const int l   = tid & 31;

    const int nhalf = blockIdx.x & 1;
    const int t  = blockIdx.x >> 1;
    const int b  = t >> 4;
    const int h0 = (t & 15) * 4;          // 4 output rows h0..h0+3

    const int mw = wid & 3;               // m-warp: pixels mw*64..+63
    const int nw = wid >> 2;              // n-warp: couts  nw*64..+63
    const int m0w = mw * 64;
    const int n0w = nw * 64;

    // ---- prologue: rows buffer (6 padded rows) + first two W tiles ----
    {
        const char* srcR = reinterpret_cast<const char*>(
            g_Xp + ((size_t)(b * HP + h0) * HP) * CIN);
        for (int i = tid; i < 6 * HP * 16; i += 256)          // 6336 x 16B
            cpa16(sRows + i * 16, srcR + (size_t)i * 16);
        const char* srcW = reinterpret_cast<const char*>(g_Wsw) + (size_t)nhalf * 32768;
        for (int i = tid; i < 2048; i += 256)                 // W shift 0
            cpa16(sW + i * 16, srcW + (size_t)i * 16);
        CP_COMMIT();
        for (int i = tid; i < 2048; i += 256)                 // W shift 1
            cpa16(sW + WBUF_SZ + i * 16, srcW + 65536 + (size_t)i * 16);
        CP_COMMIT();
    }

    // ---- per-lane invariants ----
    const int hiA = l >> 4;               // A k-half select
    const int pl  = l & 15;               // A pixel-in-tile
    int rI[4], wI[4];
    #pragma unroll
    for (int i = 0; i < 4; i++) {
        int m = m0w + i * 16 + pl;
        rI[i] = m >> 6;                   // output row in tile (0..3)
        wI[i] = m & 63;
    }
    const int hiB  = (l >> 3) & 1;        // B k-half select
    const int keyB = l & 7;
    const int bRow = (l & 7) + ((l >> 4) << 3);
    uint32_t bRowOff[4];
    #pragma unroll
    for (int j = 0; j < 4; j++)
        bRowOff[j] = (uint32_t)(n0w + j * 16 + bRow) * 256u;

    float acc[4][8][4];
    #pragma unroll
    for (int i = 0; i < 4; i++)
        #pragma unroll
        for (int j = 0; j < 8; j++)
            #pragma unroll
            for (int q = 0; q < 4; q++) acc[i][j][q] = 0.0f;

    const char* srcW = reinterpret_cast<const char*>(g_Wsw) + (size_t)nhalf * 32768;

    // ---- main loop over 9 kernel shifts ----
    for (int s = 0; s < 9; s++) {
        // wait for rows + W[s]; W[s+1] may stay in flight
        if (s < 8) { CP_WAIT(1); } else { CP_WAIT(0); }
        __syncthreads();

        // prefetch W[s+2] into buf[(s+2)%3] (safe: top barrier bounds warp skew)
        if (s + 2 <= 8) {
            uint32_t dst = sW + (uint32_t)((s + 2) % 3) * WBUF_SZ;
            const char* src = srcW + (size_t)(s + 2) * 65536;
            for (int i = tid; i < 2048; i += 256)
                cpa16(dst + i * 16, src + (size_t)i * 16);
            CP_COMMIT();
        }

        const int kh = s / 3, kw = s - 3 * kh;
        uint32_t aB[4]; int aK[4];
        #pragma unroll
        for (int i = 0; i < 4; i++) {
            int lr = rI[i] + kh;
            int pc = wI[i] + kw;
            aB[i] = sRows + (uint32_t)(lr * HP + pc) * 256u;
            aK[i] = ((h0 + lr) * HP + pc) & 7;
        }
        const uint32_t wBuf = sW + (uint32_t)(s % 3) * WBUF_SZ;

        #pragma unroll
        for (int kc = 0; kc < 8; kc++) {
            uint32_t a[4][4];
            #pragma unroll
            for (int i = 0; i < 4; i++)
                ldsm4(a[i], aB[i] + (uint32_t)((((kc << 1) + hiA) ^ aK[i]) << 4));
            const uint32_t offB = (uint32_t)((((kc << 1) + hiB) ^ keyB) << 4);
            #pragma unroll
            for (int j = 0; j < 4; j++) {
                uint32_t br[4];            // {b0,b1} of n-tile 2j and 2j+1
                ldsm4(br, wBuf + bRowOff[j] + offB);
                #pragma unroll
                for (int i = 0; i < 4; i++) {
                    mma16816(acc[i][2 * j],     a[i], br);
                    mma16816(acc[i][2 * j + 1], a[i], br + 2);
                }
            }
        }
        __syncthreads();   // all warps done with buf[s%3] + rows before reuse
    }

    // ---- epilogue: stage [co][pix] (stride 132) in SMEM, bias, coalesced f4 ----
    float* st = reinterpret_cast<float*>(smem);
    const int row_l = l >> 2;             // 0..7
    const int col_l = 2 * (l & 3);
    #pragma unroll
    for (int H = 0; H < 2; H++) {         // pixel halves 0..127 / 128..255
        if ((mw >> 1) == H) {
            #pragma unroll
            for (int i = 0; i < 4; i++) {
                int p = m0w + i * 16 + row_l - H * 128;
                #pragma unroll
                for (int j = 0; j < 8; j++) {
                    int co = n0w + j * 8 + col_l;
                    st[co * 132 + p]            = acc[i][j][0];
                    st[(co + 1) * 132 + p]      = acc[i][j][1];
                    st[co * 132 + p + 8]        = acc[i][j][2];
                    st[(co + 1) * 132 + p + 8]  = acc[i][j][3];
                }
            }
        }
        __syncthreads();
        #pragma unroll
        for (int it = 0; it < 16; it++) {
            int idx = it * 256 + tid;
            int co  = idx >> 5;
            int p4  = (idx & 31) * 4;
            float4 v = *reinterpret_cast<float4*>(&st[co * 132 + p4]);
            float bz = bias[nhalf * 128 + co];
            v.x += bz; v.y += bz; v.z += bz; v.w += bz;
            float* obase = out + ((size_t)(b * COUT + nhalf * 128 + co) * HH
                                  + (h0 + 2 * H)) * WW;
            *reinterpret_cast<float4*>(obase + p4) = v;
        }
        __syncthreads();
    }
}

// ------------------------------ launch ------------------------------

extern "C" void kernel_launch(void* const* d_in, const int* in_sizes, int n_in,
                              void* d_out, int out_size) {
    const float* X    = (const float*)d_in[0];   // [32,128,64,64]
    const float* W    = (const float*)d_in[1];   // [256,128,3,3]
    const float* bias = (const float*)d_in[2];   // [256]
    float* out = (float*)d_out;                  // [32,256,64,64]

    k_zero_xp<<<2048, 256>>>();
    k_fill_xp<<<BB * HH, 256>>>(X);
    k_prep_w<<<(9 * COUT * CIN + 255) / 256, 256>>>(W);

    cudaFuncSetAttribute(k_conv, cudaFuncAttributeMaxDynamicSharedMemorySize, SMEM_TOTAL);
    k_conv<<<1024, 256, SMEM_TOTAL>>>(out, bias);
}